// round 15
// baseline (speedup 1.0000x reference)
#include <cuda_runtime.h>
#include <cuda_fp16.h>
#include <math.h>
#include <stdint.h>

#define B_  16
#define LC  2048
#define LQ  1024
#define D_  512

// ---------------- scratch (device globals; cudaMalloc forbidden) ----------
__device__ __align__(16) __half g_E  [(size_t)B_ * LC * LQ];  // 64 MB: exp(S - M_strip)
__device__ __align__(16) __half g_At [(size_t)B_ * LQ * LC];  // A^T[b,j,i]
__device__ __align__(16) __half g_c16[(size_t)B_ * LC * D_];  // half(ctx) [b,i,d]
__device__ __align__(16) __half g_cT [(size_t)B_ * D_ * LC];  // half(ctx)^T [b,d,i]
__device__ __align__(16) __half g_qm [(size_t)LQ * D_];       // half(q*wm) [j,k]
__device__ float g_cb [B_ * LC];               // context @ wc
__device__ float g_cbp[16][B_ * LC];           // per-d-tile partial dots
__device__ float g_m  [B_ * LQ];               // global softmax max per (b,j)
__device__ float g_w2 [B_ * LQ];               // qmask[j] / Z[b,j]
__device__ float g_qmask[LQ];
__device__ float g_mp [16][B_ * LQ];           // per-128-i-strip max
__device__ float g_zp [16][B_ * LQ];           // per-128-i-strip Z (vs strip max)

// ---------------- helpers ---------------------------------------------------
__device__ __forceinline__ uint32_t smem_u32(const void* p) {
    uint32_t a;
    asm("{ .reg .u64 t; cvta.to.shared.u64 t, %1; cvt.u32.u64 %0, t; }" : "=r"(a) : "l"(p));
    return a;
}
#define CP16(sm, gp) \
    asm volatile("cp.async.cg.shared.global [%0], [%1], 16;" :: "r"(sm), "l"(gp))
#define CP_COMMIT() asm volatile("cp.async.commit_group;" ::: "memory")

#define LDSM4(r0, r1, r2, r3, addr) \
    asm volatile("ldmatrix.sync.aligned.m8n8.x4.shared.b16 {%0,%1,%2,%3}, [%4];" \
        : "=r"(r0), "=r"(r1), "=r"(r2), "=r"(r3) : "r"(addr))

#define MMAH(c, a, b) \
    asm volatile("mma.sync.aligned.m16n8k16.row.col.f32.f16.f16.f32 " \
        "{%0,%1,%2,%3},{%4,%5,%6,%7},{%8,%9},{%0,%1,%2,%3};" \
        : "+f"((c)[0]), "+f"((c)[1]), "+f"((c)[2]), "+f"((c)[3]) \
        : "r"((a)[0]), "r"((a)[1]), "r"((a)[2]), "r"((a)[3]), \
          "r"((b)[0]), "r"((b)[1]))

// ---------------- kernel: prep ctx (half + half^T) + cb partials ------------
__global__ void k_prep(const float* __restrict__ ctx, const float* __restrict__ w) {
    __shared__ float t[32][33];
    int b = blockIdx.z, i0 = blockIdx.y << 5, d0 = blockIdx.x << 5;
    int tx = threadIdx.x, ty = threadIdx.y;
    #pragma unroll
    for (int q = 0; q < 4; q++) {
        int r = ty + q * 8;
        float v = ctx[((size_t)b * LC + i0 + r) * D_ + d0 + tx];
        g_c16[((size_t)b * LC + i0 + r) * D_ + d0 + tx] = __float2half_rn(v);
        t[r][tx] = v;
    }
    __syncthreads();
    #pragma unroll
    for (int q = 0; q < 4; q++) {
        int r = ty + q * 8;
        g_cT[((size_t)b * D_ + d0 + r) * LC + i0 + tx] = __float2half_rn(t[tx][r]);
    }
    int r  = 4 * ty + (tx >> 3);
    int k4 = (tx & 7) * 4;
    const float* wc = w + d0 + k4;
    float s = t[r][k4] * wc[0] + t[r][k4 + 1] * wc[1]
            + t[r][k4 + 2] * wc[2] + t[r][k4 + 3] * wc[3];
    s += __shfl_xor_sync(~0u, s, 4);
    s += __shfl_xor_sync(~0u, s, 2);
    s += __shfl_xor_sync(~0u, s, 1);
    if ((tx & 7) == 0) g_cbp[blockIdx.x][b * LC + i0 + r] = s;
}

// ---------------- kernel: sum cb partials ------------------------------------
__global__ void k_cbsum() {
    int idx = blockIdx.x * blockDim.x + threadIdx.x;
    float s = 0.f;
    #pragma unroll
    for (int p = 0; p < 16; p++) s += g_cbp[p][idx];
    g_cb[idx] = s;
}

// ---------------- kernel: qm row (half) + qmask -------------------------------
__global__ void k_qm(const float* __restrict__ q, const float* __restrict__ w) {
    int j = blockIdx.x, t = threadIdx.x;
    const float4* q4 = (const float4*)(q + (size_t)j * D_);
    const float4* w4 = (const float4*)(w + 2 * D_);
    float4 a = q4[t], b = w4[t];
    __half2 h0 = __floats2half2_rn(a.x * b.x, a.y * b.y);
    __half2 h1 = __floats2half2_rn(a.z * b.z, a.w * b.w);
    __half* o = g_qm + (size_t)j * D_ + 4 * t;
    *(__half2*)(o)     = h0;
    *(__half2*)(o + 2) = h1;
    float s = (a.x + a.y) + (a.z + a.w);
    #pragma unroll
    for (int of = 16; of; of >>= 1) s += __shfl_xor_sync(~0u, s, of);
    __shared__ float sr[4];
    if (!(t & 31)) sr[t >> 5] = s;
    __syncthreads();
    if (!t) g_qmask[j] = ((sr[0] + sr[1] + sr[2] + sr[3]) != 0.0f) ? 1.0f : 0.0f;
}

// ---------------- unified K-major fp16 GEMM ----------------------------------
// Block 128x128, 128 threads, 4 warps of 64x64, BK=64, 3-stage cp.async
// with loads pipelined into k-steps, 2 CTAs/SM.
// MODE 0: S = c16·qm^T + cb; epilogue computes tile-wide column max M,
//         stores E = fp16(exp(S-M)) and per-strip (M, Z) partials.  No S!
// MODE 1: H = At · cT^T
#define STRD 72
#define ASZH (128 * STRD)
#define STGH (2 * ASZH)
#define GEMM_SMEM (3 * STGH * 2)   // 110592 B

template<int MODE>
__global__ __launch_bounds__(128, 2) void k_mma(float* __restrict__ gOut) {
    constexpr int KTOT = MODE ? LC : D_;
    constexpr int NKC  = KTOT / 64;

    extern __shared__ __half sh[];
    const int tid = threadIdx.x;
    const int b   = blockIdx.z;
    const int x0  = blockIdx.x * 128;
    const int y0  = blockIdx.y * 128;

    const __half* Abase = MODE ? g_At + ((size_t)b * LQ + y0) * LC
                               : g_c16 + ((size_t)b * LC + y0) * D_;
    const __half* Bbase = MODE ? g_cT + ((size_t)b * D_ + x0) * LC
                               : g_qm + (size_t)x0 * D_;

    const int lrow0 = tid >> 3;
    const int lseg  = (tid & 7) * 8;

    auto load_full = [&](int c, int st) {
        __half* dA = sh + st * STGH;
        __half* dB = dA + ASZH;
        const int k0 = c * 64;
        #pragma unroll
        for (int p = 0; p < 8; p++) {
            int row = lrow0 + p * 16;
            CP16(smem_u32(dA + row * STRD + lseg),
                 Abase + (size_t)row * KTOT + k0 + lseg);
        }
        #pragma unroll
        for (int p = 0; p < 8; p++) {
            int row = lrow0 + p * 16;
            CP16(smem_u32(dB + row * STRD + lseg),
                 Bbase + (size_t)row * KTOT + k0 + lseg);
        }
    };

    const int lane  = tid & 31, wrp = tid >> 5;
    const int mbase = (wrp & 1) * 64;
    const int nbase = (wrp >> 1) * 64;
    const int lr    = lane >> 2, lk = lane & 3;

    const uint32_t aoff = ((mbase + ((lane >> 3) & 1) * 8 + (lane & 7)) * STRD
                           + ((lane >> 4) & 1) * 8) * 2;
    const uint32_t boff = ((nbase + ((lane >> 4) & 1) * 8 + (lane & 7)) * STRD
                           + ((lane >> 3) & 1) * 8) * 2;

    float acc[4][8][4];
    #pragma unroll
    for (int mt = 0; mt < 4; mt++)
        #pragma unroll
        for (int nt = 0; nt < 8; nt++)
            #pragma unroll
            for (int e = 0; e < 4; e++) acc[mt][nt][e] = 0.f;

    auto compute_load = [&](int st, bool doload, int cload, int stl) {
        const uint32_t aB = smem_u32(sh + st * STGH) + aoff;
        const uint32_t bB = smem_u32(sh + st * STGH + ASZH) + boff;
        __half* dA = sh + stl * STGH;
        __half* dB = dA + ASZH;
        const int k0 = cload * 64;
        #pragma unroll
        for (int kk = 0; kk < 4; kk++) {
            uint32_t af[4][4], bf[8][2];
            #pragma unroll
            for (int mt = 0; mt < 4; mt++)
                LDSM4(af[mt][0], af[mt][1], af[mt][2], af[mt][3],
                      aB + (mt * 16 * STRD + kk * 16) * 2);
            #pragma unroll
            for (int p = 0; p < 4; p++)
                LDSM4(bf[2 * p][0], bf[2 * p][1], bf[2 * p + 1][0], bf[2 * p + 1][1],
                      bB + (p * 16 * STRD + kk * 16) * 2);
            if (doload) {
                #pragma unroll
                for (int u = 0; u < 2; u++) {
                    int row = lrow0 + (kk * 2 + u) * 16;
                    CP16(smem_u32(dA + row * STRD + lseg),
                         Abase + (size_t)row * KTOT + k0 + lseg);
                    CP16(smem_u32(dB + row * STRD + lseg),
                         Bbase + (size_t)row * KTOT + k0 + lseg);
                }
            }
            #pragma unroll
            for (int mt = 0; mt < 4; mt++)
                #pragma unroll
                for (int nt = 0; nt < 8; nt++)
                    MMAH(acc[mt][nt], af[mt], bf[nt]);
        }
    };

    load_full(0, 0); CP_COMMIT();
    load_full(1, 1); CP_COMMIT();
    int st_c = 0, st_l = 2;
    for (int c = 0; c < NKC; c++) {
        asm volatile("cp.async.wait_group 1;" ::: "memory");
        __syncthreads();
        compute_load(st_c, c + 2 < NKC, c + 2, st_l);
        CP_COMMIT();
        st_c = (st_c == 2) ? 0 : st_c + 1;
        st_l = (st_l == 2) ? 0 : st_l + 1;
    }

    if (MODE == 0) {
        // ---- bias add
        #pragma unroll
        for (int mt = 0; mt < 4; mt++) {
            int i = y0 + mbase + mt * 16 + lr;
            float c0 = g_cb[b * LC + i];
            float c8 = g_cb[b * LC + i + 8];
            #pragma unroll
            for (int nt = 0; nt < 8; nt++) {
                acc[mt][nt][0] += c0; acc[mt][nt][1] += c0;
                acc[mt][nt][2] += c8; acc[mt][nt][3] += c8;
            }
        }
        // ---- per-thread column max over this thread's 8 i's
        float pm[16];
        #pragma unroll
        for (int nt = 0; nt < 8; nt++) {
            float m0 = -1e30f, m1 = -1e30f;
            #pragma unroll
            for (int mt = 0; mt < 4; mt++) {
                m0 = fmaxf(m0, fmaxf(acc[mt][nt][0], acc[mt][nt][2]));
                m1 = fmaxf(m1, fmaxf(acc[mt][nt][1], acc[mt][nt][3]));
            }
            pm[2 * nt] = m0; pm[2 * nt + 1] = m1;
        }
        #pragma unroll
        for (int off = 4; off <= 16; off <<= 1)
            #pragma unroll
            for (int c2 = 0; c2 < 16; c2++)
                pm[c2] = fmaxf(pm[c2], __shfl_xor_sync(~0u, pm[c2], off));
        float* red = (float*)sh;   // [0..255]=max halves, [256..511]=z halves
        __syncthreads();
        if (lane < 4) {
            #pragma unroll
            for (int c2 = 0; c2 < 16; c2++) {
                int j = nbase + (c2 >> 1) * 8 + 2 * lane + (c2 & 1);
                red[(wrp & 1) * 128 + j] = pm[c2];
            }
        }
        __syncthreads();
        // ---- full tile column max
        float Mcol[16];
        #pragma unroll
        for (int c2 = 0; c2 < 16; c2++) {
            int j = nbase + (c2 >> 1) * 8 + 2 * lk + (c2 & 1);
            Mcol[c2] = fmaxf(red[j], red[128 + j]);
        }
        // ---- E = exp(S - M), write fp16, accumulate z
        float pz[16];
        #pragma unroll
        for (int c2 = 0; c2 < 16; c2++) pz[c2] = 0.f;
        #pragma unroll
        for (int mt = 0; mt < 4; mt++) {
            int i = y0 + mbase + mt * 16 + lr;
            __half* E0 = g_E + ((size_t)(b * LC + i)) * LQ + x0;
            __half* E8 = g_E + ((size_t)(b * LC + i + 8)) * LQ + x0;
            #pragma unroll
            for (int nt = 0; nt < 8; nt++) {
                int jl = nbase + nt * 8 + 2 * lk;
                float e0 = __expf(acc[mt][nt][0] - Mcol[2 * nt]);
                float e1 = __expf(acc[mt][nt][1] - Mcol[2 * nt + 1]);
                float e2 = __expf(acc[mt][nt][2] - Mcol[2 * nt]);
                float e3 = __expf(acc[mt][nt][3] - Mcol[2 * nt + 1]);
                pz[2 * nt]     += e0 + e2;
                pz[2 * nt + 1] += e1 + e3;
                *(__half2*)(E0 + jl) = __floats2half2_rn(e0, e1);
                *(__half2*)(E8 + jl) = __floats2half2_rn(e2, e3);
            }
        }
        #pragma unroll
        for (int off = 4; off <= 16; off <<= 1)
            #pragma unroll
            for (int c2 = 0; c2 < 16; c2++)
                pz[c2] += __shfl_xor_sync(~0u, pz[c2], off);
        if (lane < 4) {
            #pragma unroll
            for (int c2 = 0; c2 < 16; c2++) {
                int j = nbase + (c2 >> 1) * 8 + 2 * lane + (c2 & 1);
                red[256 + (wrp & 1) * 128 + j] = pz[c2];
            }
        }
        __syncthreads();
        if (tid < 128) {
            float M = fmaxf(red[tid], red[128 + tid]);
            float Z = red[256 + tid] + red[384 + tid];
            g_mp[blockIdx.y][b * LQ + x0 + tid] = M;
            g_zp[blockIdx.y][b * LQ + x0 + tid] = Z;
        }
    } else {
        #pragma unroll
        for (int mt = 0; mt < 4; mt++) {
            int j = y0 + mbase + mt * 16 + lr;
            #pragma unroll
            for (int nt = 0; nt < 8; nt++) {
                int d = x0 + nbase + nt * 8 + 2 * lk;
                float2 v0 = make_float2(acc[mt][nt][0], acc[mt][nt][1]);
                float2 v1 = make_float2(acc[mt][nt][2], acc[mt][nt][3]);
                *(float2*)(gOut + ((size_t)(b * LQ + j)) * D_ + d)     = v0;
                *(float2*)(gOut + ((size_t)(b * LQ + j + 8)) * D_ + d) = v1;
            }
        }
    }
}

// ---------------- kernel: combine 16 strips ---------------------------------
__global__ void k_stats2() {
    int idx = blockIdx.x * blockDim.x + threadIdx.x;
    float M = g_mp[0][idx];
    #pragma unroll
    for (int s = 1; s < 16; s++) M = fmaxf(M, g_mp[s][idx]);
    float Z = 0.f;
    #pragma unroll
    for (int s = 0; s < 16; s++) Z += g_zp[s][idx] * __expf(g_mp[s][idx] - M);
    g_m [idx] = M;
    g_w2[idx] = g_qmask[idx & (LQ - 1)] / Z;
}

// ---------------- kernel: A^T (half) + colsum + G from E --------------------
// A[j,i] = E[i,j] * sc[j],  sc[j] = exp(M_strip - M_global) * w2  (per strip)
__global__ __launch_bounds__(256) void k_ATG(const float* __restrict__ ctx,
                                             float* __restrict__ G) {
    const int b  = blockIdx.y;
    const int i0 = blockIdx.x << 5;
    const int strip = blockIdx.x >> 2;
    const int t  = threadIdx.x;
    __shared__ float sc[LQ];
    __shared__ float As[32][33];
    __shared__ float scs[32];
    for (int k = t; k < LQ; k += 256)
        sc[k] = __expf(g_mp[strip][b * LQ + k] - g_m[b * LQ + k]) * g_w2[b * LQ + k];
    __syncthreads();

    const int ii = t >> 3;
    const int jq = (t & 7) * 4;
    float cs = 0.f;
    const __half* Erow = g_E + ((size_t)(b * LC + i0 + ii)) * LQ;

    for (int jt = 0; jt < 32; jt++) {
        int j = jt * 32 + jq;
        __half2 e01 = *(const __half2*)(Erow + j);
        __half2 e23 = *(const __half2*)(Erow + j + 2);
        float a0 = __low2float(e01)  * sc[j + 0];
        float a1 = __high2float(e01) * sc[j + 1];
        float a2 = __low2float(e23)  * sc[j + 2];
        float a3 = __high2float(e23) * sc[j + 3];
        cs += (a0 + a1) + (a2 + a3);
        As[ii][jq + 0] = a0;
        As[ii][jq + 1] = a1;
        As[ii][jq + 2] = a2;
        As[ii][jq + 3] = a3;
        __syncthreads();
        int jj = t >> 3;
        int iq = (t & 7) * 4;
        __half2 p0 = __floats2half2_rn(As[iq + 0][jj], As[iq + 1][jj]);
        __half2 p1 = __floats2half2_rn(As[iq + 2][jj], As[iq + 3][jj]);
        __half* Arow = g_At + ((size_t)(b * LQ + jt * 32 + jj)) * LC + i0 + iq;
        *(__half2*)(Arow)     = p0;
        *(__half2*)(Arow + 2) = p1;
        __syncthreads();
    }
    cs += __shfl_xor_sync(~0u, cs, 4);
    cs += __shfl_xor_sync(~0u, cs, 2);
    cs += __shfl_xor_sync(~0u, cs, 1);
    if ((t & 7) == 0) scs[ii] = cs;
    __syncthreads();
    for (int idx = t; idx < 32 * 128; idx += 256) {
        int row = idx >> 7, c = idx & 127;
        float4 v = ((const float4*)(ctx + ((size_t)(b * LC + i0 + row)) * D_))[c];
        float s = scs[row];
        float4* g4 = (float4*)(G + ((size_t)(b * LC + i0 + row)) * 2 * D_);
        g4[c] = v;
        g4[128 + c] = make_float4(v.x * s, v.y * s, v.z * s, v.w * s);
    }
}

// ---------------- launch -----------------------------------------------------
extern "C" void kernel_launch(void* const* d_in, const int* in_sizes, int n_in,
                              void* d_out, int out_size) {
    const float *ctx = nullptr, *q = nullptr, *w = nullptr;
    for (int i = 0; i < n_in; i++) {
        if      (in_sizes[i] == B_ * LC * D_) ctx = (const float*)d_in[i];
        else if (in_sizes[i] == LQ * D_)      q   = (const float*)d_in[i];
        else if (in_sizes[i] == 3 * D_)       w   = (const float*)d_in[i];
    }
    float* G = (float*)d_out;                              // (B, LC, 2D)
    float* H = (float*)d_out + (size_t)B_ * LC * 2 * D_;   // (B, LQ, D)

    cudaFuncSetAttribute(k_mma<0>, cudaFuncAttributeMaxDynamicSharedMemorySize, GEMM_SMEM);
    cudaFuncSetAttribute(k_mma<1>, cudaFuncAttributeMaxDynamicSharedMemorySize, GEMM_SMEM);

    k_prep   <<<dim3(D_ / 32, LC / 32, B_), dim3(32, 8)>>>(ctx, w);
    k_cbsum  <<<B_ * LC / 256, 256>>>();
    k_qm     <<<LQ, 128>>>(q, w);
    k_mma<0> <<<dim3(LQ / 128, LC / 128, B_), 128, GEMM_SMEM>>>(nullptr);
    k_stats2 <<<B_ * LQ / 256, 256>>>();
    k_ATG    <<<dim3(LC / 32, B_), 256>>>(ctx, G);
    k_mma<1> <<<dim3(D_ / 128, LQ / 128, B_), 128, GEMM_SMEM>>>(H);
}

// round 16
// speedup vs baseline: 1.0699x; 1.0699x over previous
#include <cuda_runtime.h>
#include <cuda_fp16.h>
#include <math.h>
#include <stdint.h>

#define B_  16
#define LC  2048
#define LQ  1024
#define D_  512

// ---------------- scratch (device globals; cudaMalloc forbidden) ----------
__device__ __align__(16) __half g_E  [(size_t)B_ * LC * LQ];  // 64 MB: exp(S - M_strip)
__device__ __align__(16) __half g_At [(size_t)B_ * LQ * LC];  // A^T[b,j,i]
__device__ __align__(16) __half g_c16[(size_t)B_ * LC * D_];  // half(ctx) [b,i,d]
__device__ __align__(16) __half g_cT [(size_t)B_ * D_ * LC];  // half(ctx)^T [b,d,i]
__device__ __align__(16) __half g_qm [(size_t)LQ * D_];       // half(q*wm) [j,k]
__device__ float g_cb [B_ * LC];               // context @ wc
__device__ float g_cbp[16][B_ * LC];           // per-d-tile partial dots
__device__ float g_m  [B_ * LQ];               // global softmax max per (b,j)
__device__ float g_w2 [B_ * LQ];               // qmask[j] / Z[b,j]
__device__ float g_qmask[LQ];
__device__ float g_mp [16][B_ * LQ];           // per-128-i-strip max
__device__ float g_zp [16][B_ * LQ];           // per-128-i-strip Z (vs strip max)

// ---------------- helpers ---------------------------------------------------
__device__ __forceinline__ uint32_t smem_u32(const void* p) {
    uint32_t a;
    asm("{ .reg .u64 t; cvta.to.shared.u64 t, %1; cvt.u32.u64 %0, t; }" : "=r"(a) : "l"(p));
    return a;
}
#define CP16(sm, gp) \
    asm volatile("cp.async.cg.shared.global [%0], [%1], 16;" :: "r"(sm), "l"(gp))
#define CP_COMMIT() asm volatile("cp.async.commit_group;" ::: "memory")

#define LDSM4(r0, r1, r2, r3, addr) \
    asm volatile("ldmatrix.sync.aligned.m8n8.x4.shared.b16 {%0,%1,%2,%3}, [%4];" \
        : "=r"(r0), "=r"(r1), "=r"(r2), "=r"(r3) : "r"(addr))

#define MMAH(c, a, b) \
    asm volatile("mma.sync.aligned.m16n8k16.row.col.f32.f16.f16.f32 " \
        "{%0,%1,%2,%3},{%4,%5,%6,%7},{%8,%9},{%0,%1,%2,%3};" \
        : "+f"((c)[0]), "+f"((c)[1]), "+f"((c)[2]), "+f"((c)[3]) \
        : "r"((a)[0]), "r"((a)[1]), "r"((a)[2]), "r"((a)[3]), \
          "r"((b)[0]), "r"((b)[1]))

// ---------------- kernel: prep ctx (half + half^T) + cb partials ------------
__global__ void k_prep(const float* __restrict__ ctx, const float* __restrict__ w) {
    __shared__ float t[32][33];
    int b = blockIdx.z, i0 = blockIdx.y << 5, d0 = blockIdx.x << 5;
    int tx = threadIdx.x, ty = threadIdx.y;
    #pragma unroll
    for (int q = 0; q < 4; q++) {
        int r = ty + q * 8;
        float v = ctx[((size_t)b * LC + i0 + r) * D_ + d0 + tx];
        g_c16[((size_t)b * LC + i0 + r) * D_ + d0 + tx] = __float2half_rn(v);
        t[r][tx] = v;
    }
    __syncthreads();
    #pragma unroll
    for (int q = 0; q < 4; q++) {
        int r = ty + q * 8;
        g_cT[((size_t)b * D_ + d0 + r) * LC + i0 + tx] = __float2half_rn(t[tx][r]);
    }
    int r  = 4 * ty + (tx >> 3);
    int k4 = (tx & 7) * 4;
    const float* wc = w + d0 + k4;
    float s = t[r][k4] * wc[0] + t[r][k4 + 1] * wc[1]
            + t[r][k4 + 2] * wc[2] + t[r][k4 + 3] * wc[3];
    s += __shfl_xor_sync(~0u, s, 4);
    s += __shfl_xor_sync(~0u, s, 2);
    s += __shfl_xor_sync(~0u, s, 1);
    if ((tx & 7) == 0) g_cbp[blockIdx.x][b * LC + i0 + r] = s;
}

// ---------------- kernel: sum cb partials ------------------------------------
__global__ void k_cbsum() {
    int idx = blockIdx.x * blockDim.x + threadIdx.x;
    float s = 0.f;
    #pragma unroll
    for (int p = 0; p < 16; p++) s += g_cbp[p][idx];
    g_cb[idx] = s;
}

// ---------------- kernel: qm row (half) + qmask -------------------------------
__global__ void k_qm(const float* __restrict__ q, const float* __restrict__ w) {
    int j = blockIdx.x, t = threadIdx.x;
    const float4* q4 = (const float4*)(q + (size_t)j * D_);
    const float4* w4 = (const float4*)(w + 2 * D_);
    float4 a = q4[t], b = w4[t];
    __half2 h0 = __floats2half2_rn(a.x * b.x, a.y * b.y);
    __half2 h1 = __floats2half2_rn(a.z * b.z, a.w * b.w);
    __half* o = g_qm + (size_t)j * D_ + 4 * t;
    *(__half2*)(o)     = h0;
    *(__half2*)(o + 2) = h1;
    float s = (a.x + a.y) + (a.z + a.w);
    #pragma unroll
    for (int of = 16; of; of >>= 1) s += __shfl_xor_sync(~0u, s, of);
    __shared__ float sr[4];
    if (!(t & 31)) sr[t >> 5] = s;
    __syncthreads();
    if (!t) g_qmask[j] = ((sr[0] + sr[1] + sr[2] + sr[3]) != 0.0f) ? 1.0f : 0.0f;
}

// ---------------- unified K-major fp16 GEMM ----------------------------------
// Block 128x128, 128 threads, 4 warps of 64x64, BK=64, 3-stage cp.async
// with loads pipelined into k-steps, 2 CTAs/SM.
// MODE 0: S = c16·qm^T + cb; epilogue computes tile-wide column max M,
//         stores E = fp16(exp(S-M)) and per-strip (M, Z) partials.
// MODE 1: H = At · cT^T
#define STRD 72
#define ASZH (128 * STRD)
#define STGH (2 * ASZH)
#define GEMM_SMEM (3 * STGH * 2)   // 110592 B

template<int MODE>
__global__ __launch_bounds__(128, 2) void k_mma(float* __restrict__ gOut) {
    constexpr int KTOT = MODE ? LC : D_;
    constexpr int NKC  = KTOT / 64;

    extern __shared__ __half sh[];
    const int tid = threadIdx.x;
    const int b   = blockIdx.z;
    const int x0  = blockIdx.x * 128;
    const int y0  = blockIdx.y * 128;

    const __half* Abase = MODE ? g_At + ((size_t)b * LQ + y0) * LC
                               : g_c16 + ((size_t)b * LC + y0) * D_;
    const __half* Bbase = MODE ? g_cT + ((size_t)b * D_ + x0) * LC
                               : g_qm + (size_t)x0 * D_;

    const int lrow0 = tid >> 3;
    const int lseg  = (tid & 7) * 8;

    auto load_full = [&](int c, int st) {
        __half* dA = sh + st * STGH;
        __half* dB = dA + ASZH;
        const int k0 = c * 64;
        #pragma unroll
        for (int p = 0; p < 8; p++) {
            int row = lrow0 + p * 16;
            CP16(smem_u32(dA + row * STRD + lseg),
                 Abase + (size_t)row * KTOT + k0 + lseg);
        }
        #pragma unroll
        for (int p = 0; p < 8; p++) {
            int row = lrow0 + p * 16;
            CP16(smem_u32(dB + row * STRD + lseg),
                 Bbase + (size_t)row * KTOT + k0 + lseg);
        }
    };

    const int lane  = tid & 31, wrp = tid >> 5;
    const int mbase = (wrp & 1) * 64;
    const int nbase = (wrp >> 1) * 64;
    const int lr    = lane >> 2, lk = lane & 3;

    const uint32_t aoff = ((mbase + ((lane >> 3) & 1) * 8 + (lane & 7)) * STRD
                           + ((lane >> 4) & 1) * 8) * 2;
    const uint32_t boff = ((nbase + ((lane >> 4) & 1) * 8 + (lane & 7)) * STRD
                           + ((lane >> 3) & 1) * 8) * 2;

    float acc[4][8][4];
    #pragma unroll
    for (int mt = 0; mt < 4; mt++)
        #pragma unroll
        for (int nt = 0; nt < 8; nt++)
            #pragma unroll
            for (int e = 0; e < 4; e++) acc[mt][nt][e] = 0.f;

    auto compute_load = [&](int st, bool doload, int cload, int stl) {
        const uint32_t aB = smem_u32(sh + st * STGH) + aoff;
        const uint32_t bB = smem_u32(sh + st * STGH + ASZH) + boff;
        __half* dA = sh + stl * STGH;
        __half* dB = dA + ASZH;
        const int k0 = cload * 64;
        #pragma unroll
        for (int kk = 0; kk < 4; kk++) {
            uint32_t af[4][4], bf[8][2];
            #pragma unroll
            for (int mt = 0; mt < 4; mt++)
                LDSM4(af[mt][0], af[mt][1], af[mt][2], af[mt][3],
                      aB + (mt * 16 * STRD + kk * 16) * 2);
            #pragma unroll
            for (int p = 0; p < 4; p++)
                LDSM4(bf[2 * p][0], bf[2 * p][1], bf[2 * p + 1][0], bf[2 * p + 1][1],
                      bB + (p * 16 * STRD + kk * 16) * 2);
            if (doload) {
                #pragma unroll
                for (int u = 0; u < 2; u++) {
                    int row = lrow0 + (kk * 2 + u) * 16;
                    CP16(smem_u32(dA + row * STRD + lseg),
                         Abase + (size_t)row * KTOT + k0 + lseg);
                    CP16(smem_u32(dB + row * STRD + lseg),
                         Bbase + (size_t)row * KTOT + k0 + lseg);
                }
            }
            #pragma unroll
            for (int mt = 0; mt < 4; mt++)
                #pragma unroll
                for (int nt = 0; nt < 8; nt++)
                    MMAH(acc[mt][nt], af[mt], bf[nt]);
        }
    };

    load_full(0, 0); CP_COMMIT();
    load_full(1, 1); CP_COMMIT();
    int st_c = 0, st_l = 2;
    for (int c = 0; c < NKC; c++) {
        asm volatile("cp.async.wait_group 1;" ::: "memory");
        __syncthreads();
        compute_load(st_c, c + 2 < NKC, c + 2, st_l);
        CP_COMMIT();
        st_c = (st_c == 2) ? 0 : st_c + 1;
        st_l = (st_l == 2) ? 0 : st_l + 1;
    }

    if (MODE == 0) {
        // ---- bias add
        #pragma unroll
        for (int mt = 0; mt < 4; mt++) {
            int i = y0 + mbase + mt * 16 + lr;
            float c0 = g_cb[b * LC + i];
            float c8 = g_cb[b * LC + i + 8];
            #pragma unroll
            for (int nt = 0; nt < 8; nt++) {
                acc[mt][nt][0] += c0; acc[mt][nt][1] += c0;
                acc[mt][nt][2] += c8; acc[mt][nt][3] += c8;
            }
        }
        // ---- per-thread column max
        float pm[16];
        #pragma unroll
        for (int nt = 0; nt < 8; nt++) {
            float m0 = -1e30f, m1 = -1e30f;
            #pragma unroll
            for (int mt = 0; mt < 4; mt++) {
                m0 = fmaxf(m0, fmaxf(acc[mt][nt][0], acc[mt][nt][2]));
                m1 = fmaxf(m1, fmaxf(acc[mt][nt][1], acc[mt][nt][3]));
            }
            pm[2 * nt] = m0; pm[2 * nt + 1] = m1;
        }
        #pragma unroll
        for (int off = 4; off <= 16; off <<= 1)
            #pragma unroll
            for (int c2 = 0; c2 < 16; c2++)
                pm[c2] = fmaxf(pm[c2], __shfl_xor_sync(~0u, pm[c2], off));
        float* red = (float*)sh;
        __syncthreads();
        if (lane < 4) {
            #pragma unroll
            for (int c2 = 0; c2 < 16; c2++) {
                int j = nbase + (c2 >> 1) * 8 + 2 * lane + (c2 & 1);
                red[(wrp & 1) * 128 + j] = pm[c2];
            }
        }
        __syncthreads();
        float Mcol[16];
        #pragma unroll
        for (int c2 = 0; c2 < 16; c2++) {
            int j = nbase + (c2 >> 1) * 8 + 2 * lk + (c2 & 1);
            Mcol[c2] = fmaxf(red[j], red[128 + j]);
        }
        // ---- E = exp(S - M), write fp16, accumulate z
        float pz[16];
        #pragma unroll
        for (int c2 = 0; c2 < 16; c2++) pz[c2] = 0.f;
        #pragma unroll
        for (int mt = 0; mt < 4; mt++) {
            int i = y0 + mbase + mt * 16 + lr;
            __half* E0 = g_E + ((size_t)(b * LC + i)) * LQ + x0;
            __half* E8 = g_E + ((size_t)(b * LC + i + 8)) * LQ + x0;
            #pragma unroll
            for (int nt = 0; nt < 8; nt++) {
                int jl = nbase + nt * 8 + 2 * lk;
                float e0 = __expf(acc[mt][nt][0] - Mcol[2 * nt]);
                float e1 = __expf(acc[mt][nt][1] - Mcol[2 * nt + 1]);
                float e2 = __expf(acc[mt][nt][2] - Mcol[2 * nt]);
                float e3 = __expf(acc[mt][nt][3] - Mcol[2 * nt + 1]);
                pz[2 * nt]     += e0 + e2;
                pz[2 * nt + 1] += e1 + e3;
                *(__half2*)(E0 + jl) = __floats2half2_rn(e0, e1);
                *(__half2*)(E8 + jl) = __floats2half2_rn(e2, e3);
            }
        }
        #pragma unroll
        for (int off = 4; off <= 16; off <<= 1)
            #pragma unroll
            for (int c2 = 0; c2 < 16; c2++)
                pz[c2] += __shfl_xor_sync(~0u, pz[c2], off);
        if (lane < 4) {
            #pragma unroll
            for (int c2 = 0; c2 < 16; c2++) {
                int j = nbase + (c2 >> 1) * 8 + 2 * lane + (c2 & 1);
                red[256 + (wrp & 1) * 128 + j] = pz[c2];
            }
        }
        __syncthreads();
        if (tid < 128) {
            float M = fmaxf(red[tid], red[128 + tid]);
            float Z = red[256 + tid] + red[384 + tid];
            g_mp[blockIdx.y][b * LQ + x0 + tid] = M;
            g_zp[blockIdx.y][b * LQ + x0 + tid] = Z;
        }
    } else {
        #pragma unroll
        for (int mt = 0; mt < 4; mt++) {
            int j = y0 + mbase + mt * 16 + lr;
            #pragma unroll
            for (int nt = 0; nt < 8; nt++) {
                int d = x0 + nbase + nt * 8 + 2 * lk;
                float2 v0 = make_float2(acc[mt][nt][0], acc[mt][nt][1]);
                float2 v1 = make_float2(acc[mt][nt][2], acc[mt][nt][3]);
                *(float2*)(gOut + ((size_t)(b * LQ + j)) * D_ + d)     = v0;
                *(float2*)(gOut + ((size_t)(b * LQ + j + 8)) * D_ + d) = v1;
            }
        }
    }
}

// ---------------- kernel: combine 16 strips ---------------------------------
__global__ void k_stats2() {
    int idx = blockIdx.x * blockDim.x + threadIdx.x;
    float M = g_mp[0][idx];
    #pragma unroll
    for (int s = 1; s < 16; s++) M = fmaxf(M, g_mp[s][idx]);
    float Z = 0.f;
    #pragma unroll
    for (int s = 0; s < 16; s++) Z += g_zp[s][idx] * __expf(g_mp[s][idx] - M);
    g_m [idx] = M;
    g_w2[idx] = g_qmask[idx & (LQ - 1)] / Z;
}

// ---------------- kernel: A^T (half) + colsum + G from E --------------------
// 64-j passes: float4 E loads (8 halves), As[32][73] staging (conflict-free
// column gather: stride 73 mod 32 = 9), vectorized 16B At stores.
// A[j,i] = E[i,j] * sc[j],  sc[j] = exp(M_strip - M_global) * w2 (per strip)
__global__ __launch_bounds__(256) void k_ATG(const float* __restrict__ ctx,
                                             float* __restrict__ G) {
    const int b  = blockIdx.y;
    const int i0 = blockIdx.x << 5;
    const int strip = blockIdx.x >> 2;
    const int t  = threadIdx.x;
    __shared__ float sc[LQ];
    __shared__ float As[32][73];
    __shared__ float scs[32];
    for (int k = t; k < LQ; k += 256)
        sc[k] = __expf(g_mp[strip][b * LQ + k] - g_m[b * LQ + k]) * g_w2[b * LQ + k];
    __syncthreads();

    const int ii = t >> 3;            // 0..31 read-phase row
    const int jq = (t & 7) * 8;       // 0..56 read-phase j offset
    const int jj = t >> 2;            // 0..63 write-phase j row
    const int iq = (t & 3) * 8;       // 0,8,16,24 write-phase i offset
    float cs = 0.f;
    const __half* Erow = g_E + ((size_t)(b * LC + i0 + ii)) * LQ;

    for (int jt = 0; jt < 16; jt++) {
        const int j0 = jt * 64;
        // read 8 E values (one float4), scale, stage
        float4 ev = *(const float4*)(Erow + j0 + jq);
        const __half2* eh = (const __half2*)&ev;
        #pragma unroll
        for (int e = 0; e < 4; e++) {
            float lo = __low2float(eh[e])  * sc[j0 + jq + 2 * e];
            float hi = __high2float(eh[e]) * sc[j0 + jq + 2 * e + 1];
            cs += lo + hi;
            As[ii][jq + 2 * e]     = lo;
            As[ii][jq + 2 * e + 1] = hi;
        }
        __syncthreads();
        // transposed write: 8 i's (16B) for j-row j0+jj
        __half2 out[4];
        #pragma unroll
        for (int e = 0; e < 4; e++)
            out[e] = __floats2half2_rn(As[iq + 2 * e][jj], As[iq + 2 * e + 1][jj]);
        *(float4*)(g_At + ((size_t)(b * LQ + j0 + jj)) * LC + i0 + iq) =
            *(float4*)out;
        __syncthreads();
    }
    cs += __shfl_xor_sync(~0u, cs, 4);
    cs += __shfl_xor_sync(~0u, cs, 2);
    cs += __shfl_xor_sync(~0u, cs, 1);
    if ((t & 7) == 0) scs[ii] = cs;
    __syncthreads();
    for (int idx = t; idx < 32 * 128; idx += 256) {
        int row = idx >> 7, c = idx & 127;
        float4 v = ((const float4*)(ctx + ((size_t)(b * LC + i0 + row)) * D_))[c];
        float s = scs[row];
        float4* g4 = (float4*)(G + ((size_t)(b * LC + i0 + row)) * 2 * D_);
        g4[c] = v;
        g4[128 + c] = make_float4(v.x * s, v.y * s, v.z * s, v.w * s);
    }
}

// ---------------- launch -----------------------------------------------------
extern "C" void kernel_launch(void* const* d_in, const int* in_sizes, int n_in,
                              void* d_out, int out_size) {
    const float *ctx = nullptr, *q = nullptr, *w = nullptr;
    for (int i = 0; i < n_in; i++) {
        if      (in_sizes[i] == B_ * LC * D_) ctx = (const float*)d_in[i];
        else if (in_sizes[i] == LQ * D_)      q   = (const float*)d_in[i];
        else if (in_sizes[i] == 3 * D_)       w   = (const float*)d_in[i];
    }
    float* G = (float*)d_out;                              // (B, LC, 2D)
    float* H = (float*)d_out + (size_t)B_ * LC * 2 * D_;   // (B, LQ, D)

    cudaFuncSetAttribute(k_mma<0>, cudaFuncAttributeMaxDynamicSharedMemorySize, GEMM_SMEM);
    cudaFuncSetAttribute(k_mma<1>, cudaFuncAttributeMaxDynamicSharedMemorySize, GEMM_SMEM);

    k_prep   <<<dim3(D_ / 32, LC / 32, B_), dim3(32, 8)>>>(ctx, w);
    k_cbsum  <<<B_ * LC / 256, 256>>>();
    k_qm     <<<LQ, 128>>>(q, w);
    k_mma<0> <<<dim3(LQ / 128, LC / 128, B_), 128, GEMM_SMEM>>>(nullptr);
    k_stats2 <<<B_ * LQ / 256, 256>>>();
    k_ATG    <<<dim3(LC / 32, B_), 256>>>(ctx, G);
    k_mma<1> <<<dim3(D_ / 128, LQ / 128, B_), 128, GEMM_SMEM>>>(H);
}